// round 7
// baseline (speedup 1.0000x reference)
#include <cuda_runtime.h>

#define WID 512
#define HEI 512
#define NPIX (WID*HEI)
#define RAD 10
#define KS 21
#define HW (WID + 2*RAD)     // 532
#define TPB 256
#define VRV 4                 // rows/thread, iteration V passes
#define NU (WID*(HEI/VRV))    // 65536
#define VR2 2                 // rows/thread, pre V passes
#define NU2 (WID*(HEI/VR2))   // 131072

typedef unsigned long long u64;

// ---------------- compile-time weights ----------------
constexpr double cexp(double x) {
    double y = x / 16.0, s = 1.0, t = 1.0;
    for (int i = 1; i < 40; i++) { t *= y / (double)i; s += t; }
    s = s * s; s = s * s; s = s * s; s = s * s;
    return s;
}
constexpr double wgd(int t) { double d = (double)(t - RAD); return cexp(-d * d / 12.5); }
constexpr double wdd(int t) { double d = (double)(t - RAD); return cexp(-d * d * 9.0 / 200.0); }
constexpr double sumw(int wh) { double s = 0; for (int i = 0; i < KS; i++) s += (wh ? wgd(i) : wdd(i)); return s; }
constexpr double pref(int wh, int n) { double s = 0; for (int i = 0; i < n; i++) s += (wh ? wgd(i) : wdd(i)); return s; }

constexpr float SD_F    = (float)sumw(0);
constexpr float SG_F    = (float)sumw(1);
constexpr float SDINV_F = (float)(1.0 / (sumw(0) * sumw(0)));

#define TAPLIST(F) F(0) F(1) F(2) F(3) F(4) F(5) F(6) F(7) F(8) F(9) F(10) \
                   F(11) F(12) F(13) F(14) F(15) F(16) F(17) F(18) F(19) F(20)
#define DWG(i) constexpr float WG_##i = (float)wgd(i);
#define DWD(i) constexpr float WD_##i = (float)wdd(i);
TAPLIST(DWG)
TAPLIST(DWD)

__device__ __forceinline__ float wG(int t) {
    switch (t) {
#define CWG(i) case i: return WG_##i;
        TAPLIST(CWG)
#undef CWG
    }
    return 0.f;
}
__device__ __forceinline__ float wD(int t) {
    switch (t) {
#define CWD(i) case i: return WD_##i;
        TAPLIST(CWD)
#undef CWD
    }
    return 0.f;
}

__constant__ float c_pD[11] = {
    (float)pref(0,0),(float)pref(0,1),(float)pref(0,2),(float)pref(0,3),(float)pref(0,4),
    (float)pref(0,5),(float)pref(0,6),(float)pref(0,7),(float)pref(0,8),(float)pref(0,9),
    (float)pref(0,10)
};
__constant__ float c_pG[11] = {
    (float)pref(1,0),(float)pref(1,1),(float)pref(1,2),(float)pref(1,3),(float)pref(1,4),
    (float)pref(1,5),(float)pref(1,6),(float)pref(1,7),(float)pref(1,8),(float)pref(1,9),
    (float)pref(1,10)
};

__device__ __forceinline__ float hsD(int x) {
    float s = SD_F;
    if (x < RAD) s -= c_pD[RAD - x];
    if (x > WID - 1 - RAD) s -= c_pD[x - (WID - 1 - RAD)];
    return s;
}
__device__ __forceinline__ float hsG(int x) {
    float s = SG_F;
    if (x < RAD) s -= c_pG[RAD - x];
    if (x > WID - 1 - RAD) s -= c_pG[x - (WID - 1 - RAD)];
    return s;
}

// ---------------- packed f32x2 helpers ----------------
__device__ __forceinline__ u64 pk2(float x, float y) {
    u64 r; asm("mov.b64 %0,{%1,%2};" : "=l"(r) : "f"(x), "f"(y)); return r;
}
__device__ __forceinline__ float2 up2(u64 v) {
    float2 o; asm("mov.b64 {%0,%1},%2;" : "=f"(o.x), "=f"(o.y) : "l"(v)); return o;
}
__device__ __forceinline__ void fma2(u64& d, u64 a, u64 b) {
    asm("fma.rn.f32x2 %0,%1,%2,%0;" : "+l"(d) : "l"(a), "l"(b));
}
__device__ __forceinline__ u64 mul2(u64 a, u64 b) {
    u64 r; asm("mul.rn.f32x2 %0,%1,%2;" : "=l"(r) : "l"(a), "l"(b)); return r;
}
__device__ __forceinline__ u64 wpc(float w) {  // (w,w) pair; constant-folds after unroll
    unsigned u = __float_as_uint(w);
    return ((u64)u << 32) | (u64)u;
}

// ---------------- static device scratch (u64 = float2 planes) ----------------
__device__ float g_gray[NPIX], g_mI[NPIX], g_iv[NPIX], g_ibn[NPIX], g_spc[NPIX];
__device__ u64 g_s12[NPIX], g_ab1[NPIX];
__device__ u64 g_Qxy[NPIX], g_Qzw[NPIX];
__device__ u64 g_t1xy[NPIX], g_t1zw[NPIX], g_t2xy[NPIX], g_t2zw[NPIX], g_t3xy[NPIX], g_t3zw[NPIX];
__device__ u64 g_a0[NPIX], g_a1p[NPIX], g_b0[NPIX], g_b1p[NPIX], g_sp0[NPIX], g_sp1[NPIX];
__device__ u64 g_z[NPIX];

// ---------------- grid barrier ----------------
__device__ unsigned g_count = 0;
__device__ unsigned g_gen   = 0;

__device__ __forceinline__ unsigned gridbar(unsigned gen, int nb) {
    unsigned next = gen + 1;
    __threadfence();
    __syncthreads();
    if (threadIdx.x == 0) {
        if (atomicAdd(&g_count, 1) == (unsigned)(nb - 1)) {
            g_count = 0;
            __threadfence();
            atomicExch(&g_gen, next);
        } else {
            volatile unsigned* ph = &g_gen;
            while (*ph != next) { __nanosleep(40); }
        }
    }
    __syncthreads();
    __threadfence();
    return next;
}

__device__ __forceinline__ float4 softmax4(float4 z) {
    float m = fmaxf(fmaxf(z.x, z.y), fmaxf(z.z, z.w));
    float ex = __expf(z.x - m), ey = __expf(z.y - m);
    float ez = __expf(z.z - m), ew = __expf(z.w - m);
    float inv = 1.f / (ex + ey + ez + ew);
    return make_float4(ex * inv, ey * inv, ez * inv, ew * inv);
}

// ---------------- the persistent kernel ----------------
__global__ void __launch_bounds__(TPB, 3)
k_crf(const float* __restrict__ img, const float4* __restrict__ unary,
      float4* __restrict__ dout, int nb) {
    __shared__ u64 sm[4 * HW];   // 17 KB
    u64* smA = sm;
    u64* smB = sm + HW;
    u64* smC = sm + 2 * HW;
    u64* smD = sm + 3 * HW;

    const int tid = threadIdx.x;
    const int gid = blockIdx.x * TPB + tid;
    const int T   = nb * TPB;

    unsigned gen;
    {
        __shared__ unsigned sg;
        if (tid == 0) sg = *(volatile unsigned*)&g_gen;
        __syncthreads();
        gen = sg;
    }

    // ---- P0: grayscale + Q0 = softmax(-unary) as channel-pair planes ----
    for (int i = gid; i < NPIX; i += T) {
        float r = img[3 * i], gg = img[3 * i + 1], b = img[3 * i + 2];
        g_gray[i] = 0.2989f * r + 0.5870f * gg + 0.1140f * b;
        float4 u = unary[i];
        float4 q = softmax4(make_float4(-u.x, -u.y, -u.z, -u.w));
        g_Qxy[i] = pk2(q.x, q.y);
        g_Qzw[i] = pk2(q.z, q.w);
    }
    gen = gridbar(gen, nb);

    // ---- P1: H conv of (gray, gray^2) -> g_s12 ----
    for (int y = blockIdx.x; y < HEI; y += nb) {
        for (int s = tid; s < HW; s += TPB) {
            int x = s - RAD;
            u64 v = 0ULL;
            if ((unsigned)x < WID) { float g = g_gray[y * WID + x]; v = pk2(g, g * g); }
            smA[s] = v;
        }
        __syncthreads();
        int x0 = tid * 2;
        u64 A0 = 0ULL, A1 = 0ULL;
#pragma unroll
        for (int j = 0; j < KS + 1; j++) {
            u64 v = smA[x0 + j];
            if (j < KS)  fma2(A0, v, wpc(wD(j)));
            if (j >= 1)  fma2(A1, v, wpc(wD(j - 1)));
        }
        int o = y * WID + x0;
        g_s12[o] = A0; g_s12[o + 1] = A1;
        __syncthreads();
    }
    gen = gridbar(gen, nb);

    // ---- P2: V conv -> meanI / invvar / (a1,b1) ----
    for (int u = gid; u < NU2; u += T) {
        int x = u & (WID - 1), y0 = (u >> 9) * VR2;
        u64 A[VR2] = {0ULL, 0ULL};
#pragma unroll
        for (int j = 0; j < KS + VR2 - 1; j++) {
            int row = y0 + j - RAD;
            u64 v = ((unsigned)row < HEI) ? g_s12[row * WID + x] : 0ULL;
#pragma unroll
            for (int r = 0; r < VR2; r++) {
                int t = j - r;
                if (t >= 0 && t < KS) fma2(A[r], v, wpc(wD(t)));
            }
        }
        float hdx = hsD(x);
#pragma unroll
        for (int r = 0; r < VR2; r++) {
            int y = y0 + r, idx = y * WID + x;
            float2 c = up2(A[r]);
            float g = g_gray[idx];
            float mI  = (c.x - g) * SDINV_F;
            float mII = (c.y - g * g) * SDINV_F;
            float mp1 = (hdx * hsD(y) - 1.f) * SDINV_F;
            float var = mII - mI * mI;
            float iv  = 1.f / (var + 1e-4f);
            float a1  = mI * (1.f - mp1) * iv;
            float b1  = mp1 - a1 * mI;
            g_mI[idx] = mI; g_iv[idx] = iv; g_ab1[idx] = pk2(a1, b1);
        }
    }
    gen = gridbar(gen, nb);

    // ---- P3: H conv of (a1,b1) -> g_s12 ----
    for (int y = blockIdx.x; y < HEI; y += nb) {
        for (int s = tid; s < HW; s += TPB) {
            int x = s - RAD;
            smA[s] = ((unsigned)x < WID) ? g_ab1[y * WID + x] : 0ULL;
        }
        __syncthreads();
        int x0 = tid * 2;
        u64 A0 = 0ULL, A1 = 0ULL;
#pragma unroll
        for (int j = 0; j < KS + 1; j++) {
            u64 v = smA[x0 + j];
            if (j < KS)  fma2(A0, v, wpc(wD(j)));
            if (j >= 1)  fma2(A1, v, wpc(wD(j - 1)));
        }
        int o = y * WID + x0;
        g_s12[o] = A0; g_s12[o + 1] = A1;
        __syncthreads();
    }
    gen = gridbar(gen, nb);

    // ---- P4: V conv -> ibn = 10/bnorm ; also precompute spc plane ----
    for (int u = gid; u < NU2; u += T) {
        int x = u & (WID - 1), y0 = (u >> 9) * VR2;
        u64 A[VR2] = {0ULL, 0ULL};
#pragma unroll
        for (int j = 0; j < KS + VR2 - 1; j++) {
            int row = y0 + j - RAD;
            u64 v = ((unsigned)row < HEI) ? g_s12[row * WID + x] : 0ULL;
#pragma unroll
            for (int r = 0; r < VR2; r++) {
                int t = j - r;
                if (t >= 0 && t < KS) fma2(A[r], v, wpc(wD(t)));
            }
        }
        float hgx = hsG(x);
#pragma unroll
        for (int r = 0; r < VR2; r++) {
            int y = y0 + r, idx = y * WID + x;
            float2 c = up2(A[r]);
            float2 ab = up2(g_ab1[idx]);
            float g = g_gray[idx];
            float gfa = (c.x - ab.x) * SDINV_F;
            float gfb = (c.y - ab.y) * SDINV_F;
            g_ibn[idx] = 10.f / (gfa * g + gfb);
            g_spc[idx] = 3.f / (hgx * hsG(y) - 1.f);
        }
    }
    gen = gridbar(gen, nb);

    // ---- 5 mean-field iterations ----
    for (int it = 0; it < 5; it++) {
        // P5: H conv of Q (G and D) and gray*Q (D) -> 6 half planes
        for (int y = blockIdx.x; y < HEI; y += nb) {
            for (int s = tid; s < HW; s += TPB) {
                int x = s - RAD;
                u64 q0 = 0ULL, q1 = 0ULL, w0 = 0ULL, w1 = 0ULL;
                if ((unsigned)x < WID) {
                    int p = y * WID + x;
                    q0 = g_Qxy[p]; q1 = g_Qzw[p];
                    float g = g_gray[p];
                    u64 gp = pk2(g, g);
                    w0 = mul2(q0, gp); w1 = mul2(q1, gp);
                }
                smA[s] = q0; smB[s] = q1; smC[s] = w0; smD[s] = w1;
            }
            __syncthreads();
            int x0 = tid * 2;
            u64 AG[2][2], AD[2][2], AI[2][2];
#pragma unroll
            for (int r = 0; r < 2; r++) {
                AG[r][0] = AG[r][1] = 0ULL;
                AD[r][0] = AD[r][1] = 0ULL;
                AI[r][0] = AI[r][1] = 0ULL;
            }
#pragma unroll
            for (int j = 0; j < KS + 1; j++) {
                u64 v0 = smA[x0 + j], v1 = smB[x0 + j];
                u64 w0 = smC[x0 + j], w1 = smD[x0 + j];
                if (j < KS) {
                    u64 pg = wpc(wG(j)), pd = wpc(wD(j));
                    fma2(AG[0][0], v0, pg); fma2(AG[0][1], v1, pg);
                    fma2(AD[0][0], v0, pd); fma2(AD[0][1], v1, pd);
                    fma2(AI[0][0], w0, pd); fma2(AI[0][1], w1, pd);
                }
                if (j >= 1) {
                    u64 pg = wpc(wG(j - 1)), pd = wpc(wD(j - 1));
                    fma2(AG[1][0], v0, pg); fma2(AG[1][1], v1, pg);
                    fma2(AD[1][0], v0, pd); fma2(AD[1][1], v1, pd);
                    fma2(AI[1][0], w0, pd); fma2(AI[1][1], w1, pd);
                }
            }
            int o = y * WID + x0;
#pragma unroll
            for (int r = 0; r < 2; r++) {
                g_t1xy[o + r] = AG[r][0]; g_t1zw[o + r] = AG[r][1];
                g_t2xy[o + r] = AD[r][0]; g_t2zw[o + r] = AD[r][1];
                g_t3xy[o + r] = AI[r][0]; g_t3zw[o + r] = AI[r][1];
            }
            __syncthreads();
        }
        gen = gridbar(gen, nb);

        // P6: V conv + elementwise -> a,b,sp half planes (two half-sweeps in one phase)
        for (int u = gid; u < 2 * NU; u += T) {
            int h  = u >> 16;
            int i2 = u & (NU - 1);
            int x = i2 & (WID - 1), y0 = (i2 >> 9) * VRV;
            const u64* t1 = h ? g_t1zw : g_t1xy;
            const u64* t2 = h ? g_t2zw : g_t2xy;
            const u64* t3 = h ? g_t3zw : g_t3xy;
            const u64* Qh = h ? g_Qzw  : g_Qxy;
            u64* ah  = h ? g_a1p : g_a0;
            u64* bh  = h ? g_b1p : g_b0;
            u64* sph = h ? g_sp1 : g_sp0;
            u64 AG[VRV], AD[VRV], AI[VRV];
#pragma unroll
            for (int r = 0; r < VRV; r++) { AG[r] = 0ULL; AD[r] = 0ULL; AI[r] = 0ULL; }
#pragma unroll
            for (int j = 0; j < KS + VRV - 1; j++) {
                int row = y0 + j - RAD;
                u64 v1 = 0ULL, v2 = 0ULL, v3 = 0ULL;
                if ((unsigned)row < HEI) {
                    int p = row * WID + x;
                    v1 = t1[p]; v2 = t2[p]; v3 = t3[p];
                }
#pragma unroll
                for (int r = 0; r < VRV; r++) {
                    int t = j - r;
                    if (t >= 0 && t < KS) {
                        fma2(AG[r], v1, wpc(wG(t)));
                        fma2(AD[r], v2, wpc(wD(t)));
                        fma2(AI[r], v3, wpc(wD(t)));
                    }
                }
            }
#pragma unroll
            for (int r = 0; r < VRV; r++) {
                int idx = (y0 + r) * WID + x;
                float2 q = up2(Qh[idx]);
                float2 ag = up2(AG[r]), ad = up2(AD[r]), ai = up2(AI[r]);
                float g = g_gray[idx], mI = g_mI[idx], iv = g_iv[idx], spc = g_spc[idx];
                float spx = (ag.x - q.x) * spc,          spy = (ag.y - q.y) * spc;
                float mpx = (ad.x - q.x) * SDINV_F,      mpy = (ad.y - q.y) * SDINV_F;
                float mix = (ai.x - g * q.x) * SDINV_F,  miy = (ai.y - g * q.y) * SDINV_F;
                float ax = (mix - mI * mpx) * iv,        ay = (miy - mI * mpy) * iv;
                float bx = mpx - ax * mI,                by = mpy - ay * mI;
                ah[idx] = pk2(ax, ay); bh[idx] = pk2(bx, by); sph[idx] = pk2(spx, spy);
            }
        }
        gen = gridbar(gen, nb);

        // P7: H conv of a,b (both halves) -> t1xy/zw, t2xy/zw
        for (int y = blockIdx.x; y < HEI; y += nb) {
            for (int s = tid; s < HW; s += TPB) {
                int x = s - RAD;
                u64 a0 = 0ULL, a1 = 0ULL, b0 = 0ULL, b1 = 0ULL;
                if ((unsigned)x < WID) {
                    int p = y * WID + x;
                    a0 = g_a0[p]; a1 = g_a1p[p]; b0 = g_b0[p]; b1 = g_b1p[p];
                }
                smA[s] = a0; smB[s] = a1; smC[s] = b0; smD[s] = b1;
            }
            __syncthreads();
            int x0 = tid * 2;
            u64 AA[2][2], AB[2][2];
#pragma unroll
            for (int r = 0; r < 2; r++) { AA[r][0] = AA[r][1] = 0ULL; AB[r][0] = AB[r][1] = 0ULL; }
#pragma unroll
            for (int j = 0; j < KS + 1; j++) {
                u64 v0 = smA[x0 + j], v1 = smB[x0 + j];
                u64 w0 = smC[x0 + j], w1 = smD[x0 + j];
                if (j < KS) {
                    u64 pd = wpc(wD(j));
                    fma2(AA[0][0], v0, pd); fma2(AA[0][1], v1, pd);
                    fma2(AB[0][0], w0, pd); fma2(AB[0][1], w1, pd);
                }
                if (j >= 1) {
                    u64 pd = wpc(wD(j - 1));
                    fma2(AA[1][0], v0, pd); fma2(AA[1][1], v1, pd);
                    fma2(AB[1][0], w0, pd); fma2(AB[1][1], w1, pd);
                }
            }
            int o = y * WID + x0;
#pragma unroll
            for (int r = 0; r < 2; r++) {
                g_t1xy[o + r] = AA[r][0]; g_t1zw[o + r] = AA[r][1];
                g_t2xy[o + r] = AB[r][0]; g_t2zw[o + r] = AB[r][1];
            }
            __syncthreads();
        }
        gen = gridbar(gen, nb);

        // P8a: V conv of half 0 + z_xy -> g_z
        for (int u = gid; u < NU; u += T) {
            int x = u & (WID - 1), y0 = (u >> 9) * VRV;
            u64 AA[VRV], AB[VRV];
#pragma unroll
            for (int r = 0; r < VRV; r++) { AA[r] = 0ULL; AB[r] = 0ULL; }
#pragma unroll
            for (int j = 0; j < KS + VRV - 1; j++) {
                int row = y0 + j - RAD;
                u64 v1 = 0ULL, v2 = 0ULL;
                if ((unsigned)row < HEI) { int p = row * WID + x; v1 = g_t1xy[p]; v2 = g_t2xy[p]; }
#pragma unroll
                for (int r = 0; r < VRV; r++) {
                    int t = j - r;
                    if (t >= 0 && t < KS) { fma2(AA[r], v1, wpc(wD(t))); fma2(AB[r], v2, wpc(wD(t))); }
                }
            }
#pragma unroll
            for (int r = 0; r < VRV; r++) {
                int idx = (y0 + r) * WID + x;
                float2 aa = up2(AA[r]), ab = up2(AB[r]);
                float2 av = up2(g_a0[idx]), bv = up2(g_b0[idx]), sv = up2(g_sp0[idx]);
                float2 uu = ((const float2*)unary)[2 * idx + 0];
                float g = g_gray[idx], ibn = g_ibn[idx];
                float zx = sv.x + ((aa.x - av.x) * SDINV_F * g + (ab.x - bv.x) * SDINV_F) * ibn - uu.x;
                float zy = sv.y + ((aa.y - av.y) * SDINV_F * g + (ab.y - bv.y) * SDINV_F) * ibn - uu.y;
                g_z[idx] = pk2(zx, zy);
            }
        }
        gen = gridbar(gen, nb);

        // P8b: V conv of half 1 + softmax -> Q planes (or dout)
        for (int u = gid; u < NU; u += T) {
            int x = u & (WID - 1), y0 = (u >> 9) * VRV;
            u64 AA[VRV], AB[VRV];
#pragma unroll
            for (int r = 0; r < VRV; r++) { AA[r] = 0ULL; AB[r] = 0ULL; }
#pragma unroll
            for (int j = 0; j < KS + VRV - 1; j++) {
                int row = y0 + j - RAD;
                u64 v1 = 0ULL, v2 = 0ULL;
                if ((unsigned)row < HEI) { int p = row * WID + x; v1 = g_t1zw[p]; v2 = g_t2zw[p]; }
#pragma unroll
                for (int r = 0; r < VRV; r++) {
                    int t = j - r;
                    if (t >= 0 && t < KS) { fma2(AA[r], v1, wpc(wD(t))); fma2(AB[r], v2, wpc(wD(t))); }
                }
            }
#pragma unroll
            for (int r = 0; r < VRV; r++) {
                int idx = (y0 + r) * WID + x;
                float2 aa = up2(AA[r]), ab = up2(AB[r]);
                float2 av = up2(g_a1p[idx]), bv = up2(g_b1p[idx]), sv = up2(g_sp1[idx]);
                float2 uu = ((const float2*)unary)[2 * idx + 1];
                float g = g_gray[idx], ibn = g_ibn[idx];
                float zz = sv.x + ((aa.x - av.x) * SDINV_F * g + (ab.x - bv.x) * SDINV_F) * ibn - uu.x;
                float zw = sv.y + ((aa.y - av.y) * SDINV_F * g + (ab.y - bv.y) * SDINV_F) * ibn - uu.y;
                float2 zf = up2(g_z[idx]);
                float4 q = softmax4(make_float4(zf.x, zf.y, zz, zw));
                if (it == 4) {
                    dout[idx] = q;
                } else {
                    g_Qxy[idx] = pk2(q.x, q.y);
                    g_Qzw[idx] = pk2(q.z, q.w);
                }
            }
        }
        if (it < 4) gen = gridbar(gen, nb);
    }
}

// ---------------- launch ----------------
extern "C" void kernel_launch(void* const* d_in, const int* in_sizes, int n_in,
                              void* d_out, int out_size) {
    const float* unary = nullptr;
    const float* image = nullptr;
    for (int i = 0; i < n_in; i++) {
        if (in_sizes[i] == NPIX * 4) unary = (const float*)d_in[i];
        else if (in_sizes[i] == NPIX * 3) image = (const float*)d_in[i];
    }

    int sms = 0, occ = 0;
    cudaDeviceGetAttribute(&sms, cudaDevAttrMultiProcessorCount, 0);
    cudaOccupancyMaxActiveBlocksPerMultiprocessor(&occ, k_crf, TPB, 0);
    if (sms <= 0) sms = 148;
    if (occ <= 0) occ = 1;
    int nb = sms * occ;
    if (nb > 1024) nb = 1024;

    k_crf<<<nb, TPB>>>(image, (const float4*)unary, (float4*)d_out, nb);
}

// round 8
// speedup vs baseline: 1.0190x; 1.0190x over previous
#include <cuda_runtime.h>

#define WID 512
#define HEI 512
#define NPIX (WID*HEI)
#define RAD 10
#define KS 21
#define TPB 256
#define TSX 32
#define TSY 16
#define TINX 52
#define TINY 36
#define SINP 53                 // padded input tile stride (in float2)
#define SHP  33                 // padded H-buffer stride (in float2)
#define NTX (WID/TSX)           // 16
#define NTY (HEI/TSY)           // 32
#define NTILES (NTX*NTY)        // 512
#define NELEM (TINY*SINP)       // 1908

// smem layout (bytes) — overlap-packed per phase
#define OFF_IN0   0                       // float2[NELEM] = 15264
#define OFF_GRAY  15264                   // float[NELEM]  = 7632   (PhaseA)
#define OFF_INB   15264                   // float2[NELEM] = 15264  (PhaseB second input)
#define OFF_AH0   22896                   // PhaseA/Pre H buffers: float2[TINY*SHP]=9504
#define OFF_AH1   32400
#define OFF_AH2   41904
#define OFF_BH0   30528                   // PhaseB H buffers
#define OFF_BH1   40032
#define SMEM_BYTES 51408

typedef unsigned long long u64;

// ---------------- compile-time weights ----------------
constexpr double cexp(double x) {
    double y = x / 16.0, s = 1.0, t = 1.0;
    for (int i = 1; i < 40; i++) { t *= y / (double)i; s += t; }
    s = s * s; s = s * s; s = s * s; s = s * s;
    return s;
}
constexpr double wgd(int t) { double d = (double)(t - RAD); return cexp(-d * d / 12.5); }
constexpr double wdd(int t) { double d = (double)(t - RAD); return cexp(-d * d * 9.0 / 200.0); }
constexpr double sumw(int wh) { double s = 0; for (int i = 0; i < KS; i++) s += (wh ? wgd(i) : wdd(i)); return s; }
constexpr double pref(int wh, int n) { double s = 0; for (int i = 0; i < n; i++) s += (wh ? wgd(i) : wdd(i)); return s; }

constexpr float SD_F    = (float)sumw(0);
constexpr float SG_F    = (float)sumw(1);
constexpr float SDINV_F = (float)(1.0 / (sumw(0) * sumw(0)));

#define TAPLIST(F) F(0) F(1) F(2) F(3) F(4) F(5) F(6) F(7) F(8) F(9) F(10) \
                   F(11) F(12) F(13) F(14) F(15) F(16) F(17) F(18) F(19) F(20)
#define DWG(i) constexpr float WG_##i = (float)wgd(i);
#define DWD(i) constexpr float WD_##i = (float)wdd(i);
TAPLIST(DWG)
TAPLIST(DWD)

__device__ __forceinline__ float wG(int t) {
    switch (t) {
#define CWG(i) case i: return WG_##i;
        TAPLIST(CWG)
#undef CWG
    }
    return 0.f;
}
__device__ __forceinline__ float wD(int t) {
    switch (t) {
#define CWD(i) case i: return WD_##i;
        TAPLIST(CWD)
#undef CWD
    }
    return 0.f;
}

__constant__ float c_pD[11] = {
    (float)pref(0,0),(float)pref(0,1),(float)pref(0,2),(float)pref(0,3),(float)pref(0,4),
    (float)pref(0,5),(float)pref(0,6),(float)pref(0,7),(float)pref(0,8),(float)pref(0,9),
    (float)pref(0,10)
};
__constant__ float c_pG[11] = {
    (float)pref(1,0),(float)pref(1,1),(float)pref(1,2),(float)pref(1,3),(float)pref(1,4),
    (float)pref(1,5),(float)pref(1,6),(float)pref(1,7),(float)pref(1,8),(float)pref(1,9),
    (float)pref(1,10)
};

__device__ __forceinline__ float hsD(int x) {
    float s = SD_F;
    if (x < RAD) s -= c_pD[RAD - x];
    if (x > WID - 1 - RAD) s -= c_pD[x - (WID - 1 - RAD)];
    return s;
}
__device__ __forceinline__ float hsG(int x) {
    float s = SG_F;
    if (x < RAD) s -= c_pG[RAD - x];
    if (x > WID - 1 - RAD) s -= c_pG[x - (WID - 1 - RAD)];
    return s;
}

// ---------------- static device planes ----------------
__device__ float  g_gray[NPIX], g_mI[NPIX], g_iv[NPIX], g_ibn[NPIX], g_spc[NPIX];
__device__ float2 g_ab1[NPIX];
__device__ float2 g_Qxy[NPIX], g_Qzw[NPIX];
__device__ float2 g_a0[NPIX], g_a1p[NPIX], g_b0[NPIX], g_b1p[NPIX], g_sp0[NPIX], g_sp1[NPIX];

// ---------------- grid barrier ----------------
__device__ unsigned g_count = 0;
__device__ unsigned g_gen   = 0;

__device__ __forceinline__ unsigned gridbar(unsigned gen, int nb) {
    unsigned next = gen + 1;
    __threadfence();
    __syncthreads();
    if (threadIdx.x == 0) {
        if (atomicAdd(&g_count, 1) == (unsigned)(nb - 1)) {
            g_count = 0;
            __threadfence();
            atomicExch(&g_gen, next);
        } else {
            volatile unsigned* ph = &g_gen;
            while (*ph != next) { __nanosleep(40); }
        }
    }
    __syncthreads();
    __threadfence();
    return next;
}

__device__ __forceinline__ float4 softmax4(float4 z) {
    float m = fmaxf(fmaxf(z.x, z.y), fmaxf(z.z, z.w));
    float ex = __expf(z.x - m), ey = __expf(z.y - m);
    float ez = __expf(z.z - m), ew = __expf(z.w - m);
    float inv = 1.f / (ex + ey + ez + ew);
    return make_float4(ex * inv, ey * inv, ez * inv, ew * inv);
}

// load a float2 halo tile (zero-padded) from a plane
__device__ __forceinline__ void load_tile(float2* dst, const float2* src,
                                          int X0, int Y0, int tid) {
    for (int s = tid; s < NELEM; s += TPB) {
        int r = s / SINP, c = s - r * SINP;
        int gx = X0 + c - RAD, gy = Y0 + r - RAD;
        float2 v = make_float2(0.f, 0.f);
        if (c < TINX && (unsigned)gx < WID && (unsigned)gy < HEI) v = src[gy * WID + gx];
        dst[s] = v;
    }
}

// ---------------- the persistent kernel ----------------
__global__ void __launch_bounds__(TPB, 4)
k_crf(const float* __restrict__ img, const float4* __restrict__ unary,
      float4* __restrict__ dout, int nb) {
    extern __shared__ char dsm[];
    float2* sIn  = (float2*)(dsm + OFF_IN0);
    float*  sg   = (float*)(dsm + OFF_GRAY);
    float2* sInB = (float2*)(dsm + OFF_INB);
    float2* aH0  = (float2*)(dsm + OFF_AH0);
    float2* aH1  = (float2*)(dsm + OFF_AH1);
    float2* aH2  = (float2*)(dsm + OFF_AH2);
    float2* bH0  = (float2*)(dsm + OFF_BH0);
    float2* bH1  = (float2*)(dsm + OFF_BH1);

    const int tid  = threadIdx.x;
    const int wid  = tid >> 5;
    const int lane = tid & 31;
    const int gid  = blockIdx.x * TPB + tid;
    const int T    = nb * TPB;

    unsigned gen;
    {
        __shared__ unsigned sgen;
        if (tid == 0) sgen = *(volatile unsigned*)&g_gen;
        __syncthreads();
        gen = sgen;
    }

    // ---- P0: grayscale + Q0 = softmax(-unary) ----
    for (int i = gid; i < NPIX; i += T) {
        float r = img[3 * i], gg = img[3 * i + 1], b = img[3 * i + 2];
        g_gray[i] = 0.2989f * r + 0.5870f * gg + 0.1140f * b;
        float4 u = unary[i];
        float4 q = softmax4(make_float4(-u.x, -u.y, -u.z, -u.w));
        g_Qxy[i] = make_float2(q.x, q.y);
        g_Qzw[i] = make_float2(q.z, q.w);
    }
    gen = gridbar(gen, nb);

    // ---- PreA: tiled conv2D of (gray, gray^2) -> mI, iv, (a1,b1) ----
    for (int t = blockIdx.x; t < NTILES; t += nb) {
        int X0 = (t & (NTX - 1)) * TSX, Y0 = (t >> 4) * TSY;
        for (int s = tid; s < NELEM; s += TPB) {
            int r = s / SINP, c = s - r * SINP;
            int gx = X0 + c - RAD, gy = Y0 + r - RAD;
            float2 v = make_float2(0.f, 0.f);
            if (c < TINX && (unsigned)gx < WID && (unsigned)gy < HEI) {
                float gv = g_gray[gy * WID + gx];
                v = make_float2(gv, gv * gv);
            }
            sIn[s] = v;
        }
        __syncthreads();
        // H (D weights)
        for (int gg2 = wid; gg2 < 9; gg2 += 8) {
            int r = gg2 * 4 + (lane >> 3), c0 = (lane & 7) * 4;
            float a[8] = {0,0,0,0,0,0,0,0};
            const float2* rw = sIn + r * SINP + c0;
#pragma unroll
            for (int tt2 = 0; tt2 < 24; tt2++) {
                float2 v = rw[tt2];
#pragma unroll
                for (int m = 0; m < 4; m++) {
                    int w = tt2 - m;
                    if (w >= 0 && w < KS) {
                        a[2*m]   = fmaf(wD(w), v.x, a[2*m]);
                        a[2*m+1] = fmaf(wD(w), v.y, a[2*m+1]);
                    }
                }
            }
#pragma unroll
            for (int m = 0; m < 4; m++) aH0[r * SHP + c0 + m] = make_float2(a[2*m], a[2*m+1]);
        }
        __syncthreads();
        // V + elementwise
        {
            int py0 = wid * 2;
            float A[4] = {0,0,0,0};
#pragma unroll
            for (int j = 0; j < 22; j++) {
                float2 v = aH0[(py0 + j) * SHP + lane];
#pragma unroll
                for (int m = 0; m < 2; m++) {
                    int w = j - m;
                    if (w >= 0 && w < KS) {
                        A[2*m]   = fmaf(wD(w), v.x, A[2*m]);
                        A[2*m+1] = fmaf(wD(w), v.y, A[2*m+1]);
                    }
                }
            }
            float hdx = hsD(X0 + lane);
#pragma unroll
            for (int m = 0; m < 2; m++) {
                int py = py0 + m, gy = Y0 + py, idx = gy * WID + X0 + lane;
                float2 cen = sIn[(py + RAD) * SINP + lane + RAD];
                float g = cen.x;
                float mI  = (A[2*m]   - g) * SDINV_F;
                float mII = (A[2*m+1] - g * g) * SDINV_F;
                float mp1 = (hdx * hsD(gy) - 1.f) * SDINV_F;
                float var = mII - mI * mI;
                float iv  = 1.f / (var + 1e-4f);
                float a1  = mI * (1.f - mp1) * iv;
                float b1  = mp1 - a1 * mI;
                g_mI[idx] = mI; g_iv[idx] = iv; g_ab1[idx] = make_float2(a1, b1);
            }
        }
        __syncthreads();
    }
    gen = gridbar(gen, nb);

    // ---- PreB: tiled conv2D of (a1,b1) -> ibn, spc ----
    for (int t = blockIdx.x; t < NTILES; t += nb) {
        int X0 = (t & (NTX - 1)) * TSX, Y0 = (t >> 4) * TSY;
        load_tile(sIn, g_ab1, X0, Y0, tid);
        __syncthreads();
        for (int gg2 = wid; gg2 < 9; gg2 += 8) {
            int r = gg2 * 4 + (lane >> 3), c0 = (lane & 7) * 4;
            float a[8] = {0,0,0,0,0,0,0,0};
            const float2* rw = sIn + r * SINP + c0;
#pragma unroll
            for (int tt2 = 0; tt2 < 24; tt2++) {
                float2 v = rw[tt2];
#pragma unroll
                for (int m = 0; m < 4; m++) {
                    int w = tt2 - m;
                    if (w >= 0 && w < KS) {
                        a[2*m]   = fmaf(wD(w), v.x, a[2*m]);
                        a[2*m+1] = fmaf(wD(w), v.y, a[2*m+1]);
                    }
                }
            }
#pragma unroll
            for (int m = 0; m < 4; m++) aH0[r * SHP + c0 + m] = make_float2(a[2*m], a[2*m+1]);
        }
        __syncthreads();
        {
            int py0 = wid * 2;
            float A[4] = {0,0,0,0};
#pragma unroll
            for (int j = 0; j < 22; j++) {
                float2 v = aH0[(py0 + j) * SHP + lane];
#pragma unroll
                for (int m = 0; m < 2; m++) {
                    int w = j - m;
                    if (w >= 0 && w < KS) {
                        A[2*m]   = fmaf(wD(w), v.x, A[2*m]);
                        A[2*m+1] = fmaf(wD(w), v.y, A[2*m+1]);
                    }
                }
            }
            float hgx = hsG(X0 + lane);
#pragma unroll
            for (int m = 0; m < 2; m++) {
                int py = py0 + m, gy = Y0 + py, idx = gy * WID + X0 + lane;
                float2 ab = sIn[(py + RAD) * SINP + lane + RAD];
                float g = g_gray[idx];
                float gfa = (A[2*m]   - ab.x) * SDINV_F;
                float gfb = (A[2*m+1] - ab.y) * SDINV_F;
                g_ibn[idx] = 10.f / (gfa * g + gfb);
                g_spc[idx] = 3.f / (hgx * hsG(gy) - 1.f);
            }
        }
        __syncthreads();
    }
    gen = gridbar(gen, nb);

    // ---- 5 mean-field iterations: 2 tiled phases each ----
    for (int it = 0; it < 5; it++) {
        // ===== PhaseA: conv2D(Q)x{G,D} + conv2D(grayQ)xD + elementwise -> a,b,sp =====
        for (int t = blockIdx.x; t < NTILES; t += nb) {
            int X0 = (t & (NTX - 1)) * TSX, Y0 = (t >> 4) * TSY;
            // gray tile (once per tile)
            for (int s = tid; s < NELEM; s += TPB) {
                int r = s / SINP, c = s - r * SINP;
                int gx = X0 + c - RAD, gy = Y0 + r - RAD;
                float v = 0.f;
                if (c < TINX && (unsigned)gx < WID && (unsigned)gy < HEI) v = g_gray[gy * WID + gx];
                sg[s] = v;
            }
            for (int h = 0; h < 2; h++) {
                load_tile(sIn, h ? g_Qzw : g_Qxy, X0, Y0, tid);
                __syncthreads();
                // H: 3 quantities share the input stream
                for (int gg2 = wid; gg2 < 9; gg2 += 8) {
                    int r = gg2 * 4 + (lane >> 3), c0 = (lane & 7) * 4;
                    float aD[8] = {0,0,0,0,0,0,0,0};
                    float aG[8] = {0,0,0,0,0,0,0,0};
                    float aI[8] = {0,0,0,0,0,0,0,0};
                    const float2* rw = sIn + r * SINP + c0;
                    const float*  rg = sg  + r * SINP + c0;
#pragma unroll
                    for (int tt2 = 0; tt2 < 24; tt2++) {
                        float2 v = rw[tt2];
                        float gf = rg[tt2];
                        float wx = gf * v.x, wy = gf * v.y;
#pragma unroll
                        for (int m = 0; m < 4; m++) {
                            int w = tt2 - m;
                            if (w >= 0 && w < KS) {
                                aD[2*m]   = fmaf(wD(w), v.x, aD[2*m]);
                                aD[2*m+1] = fmaf(wD(w), v.y, aD[2*m+1]);
                                aG[2*m]   = fmaf(wG(w), v.x, aG[2*m]);
                                aG[2*m+1] = fmaf(wG(w), v.y, aG[2*m+1]);
                                aI[2*m]   = fmaf(wD(w), wx, aI[2*m]);
                                aI[2*m+1] = fmaf(wD(w), wy, aI[2*m+1]);
                            }
                        }
                    }
#pragma unroll
                    for (int m = 0; m < 4; m++) {
                        aH0[r * SHP + c0 + m] = make_float2(aD[2*m], aD[2*m+1]);
                        aH1[r * SHP + c0 + m] = make_float2(aG[2*m], aG[2*m+1]);
                        aH2[r * SHP + c0 + m] = make_float2(aI[2*m], aI[2*m+1]);
                    }
                }
                __syncthreads();
                // V (3 quantities) + elementwise
                {
                    int py0 = wid * 2;
                    float AD[4] = {0,0,0,0}, AG[4] = {0,0,0,0}, AI[4] = {0,0,0,0};
#pragma unroll
                    for (int j = 0; j < 22; j++) {
                        float2 v0 = aH0[(py0 + j) * SHP + lane];
                        float2 v1 = aH1[(py0 + j) * SHP + lane];
                        float2 v2 = aH2[(py0 + j) * SHP + lane];
#pragma unroll
                        for (int m = 0; m < 2; m++) {
                            int w = j - m;
                            if (w >= 0 && w < KS) {
                                AD[2*m]   = fmaf(wD(w), v0.x, AD[2*m]);
                                AD[2*m+1] = fmaf(wD(w), v0.y, AD[2*m+1]);
                                AG[2*m]   = fmaf(wG(w), v1.x, AG[2*m]);
                                AG[2*m+1] = fmaf(wG(w), v1.y, AG[2*m+1]);
                                AI[2*m]   = fmaf(wD(w), v2.x, AI[2*m]);
                                AI[2*m+1] = fmaf(wD(w), v2.y, AI[2*m+1]);
                            }
                        }
                    }
#pragma unroll
                    for (int m = 0; m < 2; m++) {
                        int py = py0 + m, idx = (Y0 + py) * WID + X0 + lane;
                        float2 q = sIn[(py + RAD) * SINP + lane + RAD];
                        float g = sg[(py + RAD) * SINP + lane + RAD];
                        float mI = g_mI[idx], iv = g_iv[idx], spc = g_spc[idx];
                        float spx = (AG[2*m]   - q.x) * spc;
                        float spy = (AG[2*m+1] - q.y) * spc;
                        float mpx = (AD[2*m]   - q.x) * SDINV_F;
                        float mpy = (AD[2*m+1] - q.y) * SDINV_F;
                        float mix = (AI[2*m]   - g * q.x) * SDINV_F;
                        float miy = (AI[2*m+1] - g * q.y) * SDINV_F;
                        float ax = (mix - mI * mpx) * iv, ay = (miy - mI * mpy) * iv;
                        float bx = mpx - ax * mI,         by = mpy - ay * mI;
                        if (h == 0) {
                            g_a0[idx]  = make_float2(ax, ay);
                            g_b0[idx]  = make_float2(bx, by);
                            g_sp0[idx] = make_float2(spx, spy);
                        } else {
                            g_a1p[idx] = make_float2(ax, ay);
                            g_b1p[idx] = make_float2(bx, by);
                            g_sp1[idx] = make_float2(spx, spy);
                        }
                    }
                }
                __syncthreads();
            }
        }
        gen = gridbar(gen, nb);

        // ===== PhaseB: conv2D(a,b) + message + softmax -> Q / dout =====
        for (int t = blockIdx.x; t < NTILES; t += nb) {
            int X0 = (t & (NTX - 1)) * TSX, Y0 = (t >> 4) * TSY;
            float z0[4];   // half-0 logits for this thread's 2 pixels
            for (int h = 0; h < 2; h++) {
                load_tile(sIn,  h ? g_a1p : g_a0, X0, Y0, tid);
                load_tile(sInB, h ? g_b1p : g_b0, X0, Y0, tid);
                __syncthreads();
                for (int gg2 = wid; gg2 < 9; gg2 += 8) {
                    int r = gg2 * 4 + (lane >> 3), c0 = (lane & 7) * 4;
                    float aA[8] = {0,0,0,0,0,0,0,0};
                    float aB[8] = {0,0,0,0,0,0,0,0};
                    const float2* rwA = sIn  + r * SINP + c0;
                    const float2* rwB = sInB + r * SINP + c0;
#pragma unroll
                    for (int tt2 = 0; tt2 < 24; tt2++) {
                        float2 vA = rwA[tt2], vB = rwB[tt2];
#pragma unroll
                        for (int m = 0; m < 4; m++) {
                            int w = tt2 - m;
                            if (w >= 0 && w < KS) {
                                aA[2*m]   = fmaf(wD(w), vA.x, aA[2*m]);
                                aA[2*m+1] = fmaf(wD(w), vA.y, aA[2*m+1]);
                                aB[2*m]   = fmaf(wD(w), vB.x, aB[2*m]);
                                aB[2*m+1] = fmaf(wD(w), vB.y, aB[2*m+1]);
                            }
                        }
                    }
#pragma unroll
                    for (int m = 0; m < 4; m++) {
                        bH0[r * SHP + c0 + m] = make_float2(aA[2*m], aA[2*m+1]);
                        bH1[r * SHP + c0 + m] = make_float2(aB[2*m], aB[2*m+1]);
                    }
                }
                __syncthreads();
                {
                    int py0 = wid * 2;
                    float AA[4] = {0,0,0,0}, AB[4] = {0,0,0,0};
#pragma unroll
                    for (int j = 0; j < 22; j++) {
                        float2 v0 = bH0[(py0 + j) * SHP + lane];
                        float2 v1 = bH1[(py0 + j) * SHP + lane];
#pragma unroll
                        for (int m = 0; m < 2; m++) {
                            int w = j - m;
                            if (w >= 0 && w < KS) {
                                AA[2*m]   = fmaf(wD(w), v0.x, AA[2*m]);
                                AA[2*m+1] = fmaf(wD(w), v0.y, AA[2*m+1]);
                                AB[2*m]   = fmaf(wD(w), v1.x, AB[2*m]);
                                AB[2*m+1] = fmaf(wD(w), v1.y, AB[2*m+1]);
                            }
                        }
                    }
#pragma unroll
                    for (int m = 0; m < 2; m++) {
                        int py = py0 + m, idx = (Y0 + py) * WID + X0 + lane;
                        float2 ac = sIn [(py + RAD) * SINP + lane + RAD];
                        float2 bc = sInB[(py + RAD) * SINP + lane + RAD];
                        float2 sp = h ? g_sp1[idx] : g_sp0[idx];
                        float ibn = g_ibn[idx], g = g_gray[idx];
                        float2 uu = *((const float2*)unary + 2 * idx + h);
                        float zx = sp.x + ((AA[2*m]   - ac.x) * SDINV_F * g
                                         + (AB[2*m]   - bc.x) * SDINV_F) * ibn - uu.x;
                        float zy = sp.y + ((AA[2*m+1] - ac.y) * SDINV_F * g
                                         + (AB[2*m+1] - bc.y) * SDINV_F) * ibn - uu.y;
                        if (h == 0) {
                            z0[2*m] = zx; z0[2*m+1] = zy;
                        } else {
                            float4 q = softmax4(make_float4(z0[2*m], z0[2*m+1], zx, zy));
                            if (it == 4) {
                                dout[idx] = q;
                            } else {
                                g_Qxy[idx] = make_float2(q.x, q.y);
                                g_Qzw[idx] = make_float2(q.z, q.w);
                            }
                        }
                    }
                }
                __syncthreads();
            }
        }
        if (it < 4) gen = gridbar(gen, nb);
    }
}

// ---------------- launch ----------------
extern "C" void kernel_launch(void* const* d_in, const int* in_sizes, int n_in,
                              void* d_out, int out_size) {
    const float* unary = nullptr;
    const float* image = nullptr;
    for (int i = 0; i < n_in; i++) {
        if (in_sizes[i] == NPIX * 4) unary = (const float*)d_in[i];
        else if (in_sizes[i] == NPIX * 3) image = (const float*)d_in[i];
    }

    cudaFuncSetAttribute(k_crf, cudaFuncAttributeMaxDynamicSharedMemorySize, SMEM_BYTES);

    int sms = 0, occ = 0;
    cudaDeviceGetAttribute(&sms, cudaDevAttrMultiProcessorCount, 0);
    cudaOccupancyMaxActiveBlocksPerMultiprocessor(&occ, k_crf, TPB, SMEM_BYTES);
    if (sms <= 0) sms = 148;
    if (occ <= 0) occ = 1;
    int nb = sms * occ;
    if (nb > 1024) nb = 1024;

    k_crf<<<nb, TPB, SMEM_BYTES>>>(image, (const float4*)unary, (float4*)d_out, nb);
}